// round 9
// baseline (speedup 1.0000x reference)
#include <cuda_runtime.h>
#include <cstdint>
#include <cstddef>

#define NROWS 12288
#define FDIM  768
#define HDIM  512
#define ODIM  256

// Scratch (device globals: allocation-free per harness rules)
__device__ float g_x1[(size_t)NROWS * HDIM];          // 24 MB
__device__ float g_x2[(size_t)NROWS * HDIM];          // 24 MB
__device__ float g_e [(size_t)NROWS * ODIM];          // 12 MB
__device__ float g_sim[(size_t)NROWS * NROWS];        // 604 MB

// ---------------------------------------------------------------------------
// SGEMM: C[M,N] = A[M,K] * B[N,K]^T (+bias) (optional relu)
// VERBATIM round-1 source (the best-correlated variant: 1 flip).
// Tiles: 128x128x16, 256 threads, 8x8 per-thread microtile.
// ---------------------------------------------------------------------------
template<int RELU>
__global__ __launch_bounds__(256) void sgemm_abt(
    const float* __restrict__ A, const float* __restrict__ B,
    const float* __restrict__ bias, float* __restrict__ C,
    int M, int N, int K)
{
    __shared__ __align__(16) float As[16][128];
    __shared__ __align__(16) float Bs[16][128];

    const int tid = threadIdx.x;
    const int tx  = tid & 15;           // output column group
    const int ty  = tid >> 4;           // output row group
    const int mBase = blockIdx.y * 128;
    const int nBase = blockIdx.x * 128;

    const int r0 = tid >> 2;            // row within tile (0..63)
    const int q0 = (tid & 3) * 4;       // k offset (0,4,8,12)

    const float* aPtr = A + (size_t)(mBase + r0) * K + q0;
    const float* bPtr = B + (size_t)(nBase + r0) * K + q0;

    float acc[8][8];
    #pragma unroll
    for (int i = 0; i < 8; i++)
        #pragma unroll
        for (int j = 0; j < 8; j++) acc[i][j] = 0.0f;

    for (int kb = 0; kb < K; kb += 16) {
        float4 a0 = *(const float4*)(aPtr + kb);
        float4 a1 = *(const float4*)(aPtr + (size_t)64 * K + kb);
        float4 b0 = *(const float4*)(bPtr + kb);
        float4 b1 = *(const float4*)(bPtr + (size_t)64 * K + kb);

        __syncthreads();   // prior-iteration smem reads complete before overwrite
        As[q0+0][r0] = a0.x;  As[q0+1][r0] = a0.y;  As[q0+2][r0] = a0.z;  As[q0+3][r0] = a0.w;
        As[q0+0][r0+64] = a1.x; As[q0+1][r0+64] = a1.y; As[q0+2][r0+64] = a1.z; As[q0+3][r0+64] = a1.w;
        Bs[q0+0][r0] = b0.x;  Bs[q0+1][r0] = b0.y;  Bs[q0+2][r0] = b0.z;  Bs[q0+3][r0] = b0.w;
        Bs[q0+0][r0+64] = b1.x; Bs[q0+1][r0+64] = b1.y; Bs[q0+2][r0+64] = b1.z; Bs[q0+3][r0+64] = b1.w;
        __syncthreads();

        #pragma unroll
        for (int k = 0; k < 16; k++) {
            float4 av0 = *(const float4*)&As[k][ty * 8];
            float4 av1 = *(const float4*)&As[k][ty * 8 + 4];
            float4 bv0 = *(const float4*)&Bs[k][tx * 8];
            float4 bv1 = *(const float4*)&Bs[k][tx * 8 + 4];
            float a[8] = {av0.x, av0.y, av0.z, av0.w, av1.x, av1.y, av1.z, av1.w};
            float b[8] = {bv0.x, bv0.y, bv0.z, bv0.w, bv1.x, bv1.y, bv1.z, bv1.w};
            #pragma unroll
            for (int i = 0; i < 8; i++)
                #pragma unroll
                for (int j = 0; j < 8; j++)
                    acc[i][j] = fmaf(a[i], b[j], acc[i][j]);
        }
    }

    float bj[8];
    #pragma unroll
    for (int j = 0; j < 8; j++)
        bj[j] = bias ? bias[nBase + tx * 8 + j] : 0.0f;

    #pragma unroll
    for (int i = 0; i < 8; i++) {
        const int m = mBase + ty * 8 + i;
        float o[8];
        #pragma unroll
        for (int j = 0; j < 8; j++) {
            float v = acc[i][j] + bj[j];
            if (RELU) v = fmaxf(v, 0.0f);
            o[j] = v;
        }
        float* cRow = C + (size_t)m * N + nBase + tx * 8;
        *(float4*)(cRow + 0) = make_float4(o[0], o[1], o[2], o[3]);
        *(float4*)(cRow + 4) = make_float4(o[4], o[5], o[6], o[7]);
    }
}

// ---------------------------------------------------------------------------
// Row L2 normalize: e = x / max(||x||, 1e-12). One warp per 256-wide row.
// VERBATIM round-1 source — the compiler's fast-math lowering of this exact
// expression tree is the empirically best-correlated normalize (1 flip).
// ---------------------------------------------------------------------------
__global__ void l2norm_rows(const float* __restrict__ x, float* __restrict__ e)
{
    const int gw   = (blockIdx.x * blockDim.x + threadIdx.x) >> 5;
    const int lane = threadIdx.x & 31;
    if (gw >= NROWS) return;
    const float4* r = (const float4*)(x + (size_t)gw * ODIM);
    float4 v0 = r[lane];
    float4 v1 = r[lane + 32];
    float s = v0.x*v0.x + v0.y*v0.y + v0.z*v0.z + v0.w*v0.w
            + v1.x*v1.x + v1.y*v1.y + v1.z*v1.z + v1.w*v1.w;
    #pragma unroll
    for (int o = 16; o; o >>= 1) s += __shfl_xor_sync(0xFFFFFFFFu, s, o);
    const float scale = 1.0f / fmaxf(sqrtf(s), 1e-12f);
    v0.x *= scale; v0.y *= scale; v0.z *= scale; v0.w *= scale;
    v1.x *= scale; v1.y *= scale; v1.z *= scale; v1.w *= scale;
    float4* w = (float4*)(e + (size_t)gw * ODIM);
    w[lane]      = v0;
    w[lane + 32] = v1;
}

// ---------------------------------------------------------------------------
// Per-row top-31 via exact 4-pass radix select, with lax.top_k-compatible
// tie-breaking: among values bit-equal to the rank-31 threshold, keep only
// the lowest-index occurrences. One CTA per row; row cached in smem.
// ---------------------------------------------------------------------------
#define MAXEQ 64

__global__ __launch_bounds__(256) void topk_rows(const float* __restrict__ sim,
                                                 float* __restrict__ out)
{
    extern __shared__ uint32_t sh[];
    uint32_t* keys = sh;            // NROWS entries (48 KB)
    uint32_t* hist = sh + NROWS;    // 256 entries (1 KB)
    __shared__ uint32_t s_sel, s_rank;
    __shared__ int s_eqIdx[MAXEQ];
    __shared__ int s_eqCnt;
    __shared__ int s_cutoff;

    const int tid  = threadIdx.x;
    const int lane = tid & 31;
    const int row  = blockIdx.x;

    const float4* r4 = (const float4*)(sim + (size_t)row * NROWS);
    for (int i = tid; i < NROWS / 4; i += 256) {
        float4 v = r4[i];
        uint32_t u;
        u = __float_as_uint(v.x); keys[i*4+0] = (u & 0x80000000u) ? ~u : (u | 0x80000000u);
        u = __float_as_uint(v.y); keys[i*4+1] = (u & 0x80000000u) ? ~u : (u | 0x80000000u);
        u = __float_as_uint(v.z); keys[i*4+2] = (u & 0x80000000u) ? ~u : (u | 0x80000000u);
        u = __float_as_uint(v.w); keys[i*4+3] = (u & 0x80000000u) ? ~u : (u | 0x80000000u);
    }
    __syncthreads();

    uint32_t prefix = 0;
    uint32_t rank   = 31;   // KNN_K + 1 entries kept per row

    #pragma unroll
    for (int pass = 0; pass < 4; ++pass) {
        const int      shift = 24 - 8 * pass;
        const uint32_t kmask = (pass == 0) ? 0u : (0xFFFFFFFFu << (shift + 8));

        hist[tid] = 0;
        __syncthreads();

        for (int i = tid; i < NROWS; i += 256) {
            const uint32_t key = keys[i];
            const bool ok = (key & kmask) == prefix;
            const uint32_t d = ok ? ((key >> shift) & 0xFFu) : 0xFFFFFFFFu;
            const unsigned grp = __match_any_sync(0xFFFFFFFFu, d);
            if (ok && lane == (__ffs(grp) - 1))
                atomicAdd(&hist[d], (uint32_t)__popc(grp));
        }
        __syncthreads();

        if (tid == 0) {
            uint32_t c = 0; int d = 255;
            for (; d >= 0; --d) { c += hist[d]; if (c >= rank) break; }
            s_sel  = (uint32_t)d;
            s_rank = rank - (c - hist[d]);
            if (pass == 0) s_eqCnt = 0;
        }
        __syncthreads();
        prefix |= s_sel << shift;
        rank    = s_rank;
    }

    const uint32_t thresh = prefix;   // exact key of 31st-largest value
    const int need = (int)rank;       // # of ==thresh entries that belong in top-31

    // Collect indices of values bit-equal to the threshold (typically 1).
    for (int i = tid; i < NROWS; i += 256) {
        if (keys[i] == thresh) {
            int p = atomicAdd(&s_eqCnt, 1);
            if (p < MAXEQ) s_eqIdx[p] = i;
        }
    }
    __syncthreads();
    if (tid == 0) {
        int cnt = s_eqCnt < MAXEQ ? s_eqCnt : MAXEQ;
        for (int a = 1; a < cnt; a++) {          // tiny ascending insertion sort
            int v = s_eqIdx[a], b = a - 1;
            while (b >= 0 && s_eqIdx[b] > v) { s_eqIdx[b+1] = s_eqIdx[b]; b--; }
            s_eqIdx[b+1] = v;
        }
        int nd = need; if (nd > cnt) nd = cnt; if (nd < 1) nd = 1;
        s_cutoff = s_eqIdx[nd - 1];   // keep ==thresh entries with index <= cutoff
    }
    __syncthreads();
    const int cutoff = s_cutoff;

    float* orow = out + (size_t)row * NROWS;
    for (int i = tid; i < NROWS; i += 256) {
        const uint32_t key = keys[i];
        const bool kept = (key > thresh) | ((key == thresh) & (i <= cutoff));
        float v = 0.0f;
        if (kept && key > 0x80000000u)     // kept AND strictly positive (relu)
            v = __uint_as_float(key ^ 0x80000000u);
        orow[i] = v;
    }
}

// ---------------------------------------------------------------------------
extern "C" void kernel_launch(void* const* d_in, const int* in_sizes, int n_in,
                              void* d_out, int out_size)
{
    const float* features = (const float*)d_in[0];
    const float* W1 = (const float*)d_in[1];
    const float* b1 = (const float*)d_in[2];
    const float* W2 = (const float*)d_in[3];
    const float* b2 = (const float*)d_in[4];
    const float* W3 = (const float*)d_in[5];
    const float* b3 = (const float*)d_in[6];
    float* out = (float*)d_out;

    float *x1, *x2, *e, *sim;
    cudaGetSymbolAddress((void**)&x1,  g_x1);
    cudaGetSymbolAddress((void**)&x2,  g_x2);
    cudaGetSymbolAddress((void**)&e,   g_e);
    cudaGetSymbolAddress((void**)&sim, g_sim);

    cudaFuncSetAttribute(topk_rows, cudaFuncAttributeMaxDynamicSharedMemorySize,
                         (NROWS + 256) * sizeof(uint32_t));

    // MLP
    sgemm_abt<1><<<dim3(HDIM / 128, NROWS / 128), 256>>>(features, W1, b1, x1, NROWS, HDIM, FDIM);
    sgemm_abt<1><<<dim3(HDIM / 128, NROWS / 128), 256>>>(x1,       W2, b2, x2, NROWS, HDIM, HDIM);
    // x3 reuses x1's buffer (x1 is dead after layer 2)
    sgemm_abt<0><<<dim3(ODIM / 128, NROWS / 128), 256>>>(x2,       W3, b3, x1, NROWS, ODIM, HDIM);

    // L2 normalize rows -> e (round-1 verbatim)
    l2norm_rows<<<NROWS / 8, 256>>>(x1, e);

    // sim = e @ e^T  (dominant GEMM: 77 GFLOP)
    sgemm_abt<0><<<dim3(NROWS / 128, NROWS / 128), 256>>>(e, e, nullptr, sim, NROWS, NROWS, ODIM);

    // per-row exact top-31 (index tie-break) + masked relu write
    topk_rows<<<NROWS, 256, (NROWS + 256) * sizeof(uint32_t)>>>(sim, out);
}

// round 10
// speedup vs baseline: 1.3130x; 1.3130x over previous
#include <cuda_runtime.h>
#include <cstdint>
#include <cstddef>

#define NROWS 12288
#define FDIM  768
#define HDIM  512
#define ODIM  256

// Scratch (device globals: allocation-free per harness rules)
__device__ float g_x1[(size_t)NROWS * HDIM];          // 24 MB
__device__ float g_x2[(size_t)NROWS * HDIM];          // 24 MB
__device__ float g_e [(size_t)NROWS * ODIM];          // 12 MB
__device__ float g_sim[(size_t)NROWS * NROWS];        // 604 MB

// ---------------------------------------------------------------------------
// SGEMM: C[M,N] = A[M,K] * B[N,K]^T (+bias) (optional relu)
// Arithmetic verbatim from the passing round-9 kernel (k-ascending fp32 FMA
// chain). SYM=1 skips tiles below the diagonal (bx < by); the mirror kernel
// fills them with bit-identical values (fmaf(a,b,c) == fmaf(b,a,c)).
// Tiles: 128x128x16, 256 threads, 8x8 per-thread microtile.
// ---------------------------------------------------------------------------
template<int RELU, int SYM>
__global__ __launch_bounds__(256) void sgemm_abt(
    const float* __restrict__ A, const float* __restrict__ B,
    const float* __restrict__ bias, float* __restrict__ C,
    int M, int N, int K)
{
    if (SYM && blockIdx.x < blockIdx.y) return;   // lower-triangle tiles mirrored later

    __shared__ __align__(16) float As[16][128];
    __shared__ __align__(16) float Bs[16][128];

    const int tid = threadIdx.x;
    const int tx  = tid & 15;           // output column group
    const int ty  = tid >> 4;           // output row group
    const int mBase = blockIdx.y * 128;
    const int nBase = blockIdx.x * 128;

    const int r0 = tid >> 2;            // row within tile (0..63)
    const int q0 = (tid & 3) * 4;       // k offset (0,4,8,12)

    const float* aPtr = A + (size_t)(mBase + r0) * K + q0;
    const float* bPtr = B + (size_t)(nBase + r0) * K + q0;

    float acc[8][8];
    #pragma unroll
    for (int i = 0; i < 8; i++)
        #pragma unroll
        for (int j = 0; j < 8; j++) acc[i][j] = 0.0f;

    for (int kb = 0; kb < K; kb += 16) {
        float4 a0 = *(const float4*)(aPtr + kb);
        float4 a1 = *(const float4*)(aPtr + (size_t)64 * K + kb);
        float4 b0 = *(const float4*)(bPtr + kb);
        float4 b1 = *(const float4*)(bPtr + (size_t)64 * K + kb);

        __syncthreads();   // prior-iteration smem reads complete before overwrite
        As[q0+0][r0] = a0.x;  As[q0+1][r0] = a0.y;  As[q0+2][r0] = a0.z;  As[q0+3][r0] = a0.w;
        As[q0+0][r0+64] = a1.x; As[q0+1][r0+64] = a1.y; As[q0+2][r0+64] = a1.z; As[q0+3][r0+64] = a1.w;
        Bs[q0+0][r0] = b0.x;  Bs[q0+1][r0] = b0.y;  Bs[q0+2][r0] = b0.z;  Bs[q0+3][r0] = b0.w;
        Bs[q0+0][r0+64] = b1.x; Bs[q0+1][r0+64] = b1.y; Bs[q0+2][r0+64] = b1.z; Bs[q0+3][r0+64] = b1.w;
        __syncthreads();

        #pragma unroll
        for (int k = 0; k < 16; k++) {
            float4 av0 = *(const float4*)&As[k][ty * 8];
            float4 av1 = *(const float4*)&As[k][ty * 8 + 4];
            float4 bv0 = *(const float4*)&Bs[k][tx * 8];
            float4 bv1 = *(const float4*)&Bs[k][tx * 8 + 4];
            float a[8] = {av0.x, av0.y, av0.z, av0.w, av1.x, av1.y, av1.z, av1.w};
            float b[8] = {bv0.x, bv0.y, bv0.z, bv0.w, bv1.x, bv1.y, bv1.z, bv1.w};
            #pragma unroll
            for (int i = 0; i < 8; i++)
                #pragma unroll
                for (int j = 0; j < 8; j++)
                    acc[i][j] = fmaf(a[i], b[j], acc[i][j]);
        }
    }

    float bj[8];
    #pragma unroll
    for (int j = 0; j < 8; j++)
        bj[j] = bias ? bias[nBase + tx * 8 + j] : 0.0f;

    #pragma unroll
    for (int i = 0; i < 8; i++) {
        const int m = mBase + ty * 8 + i;
        float o[8];
        #pragma unroll
        for (int j = 0; j < 8; j++) {
            float v = acc[i][j] + bj[j];
            if (RELU) v = fmaxf(v, 0.0f);
            o[j] = v;
        }
        float* cRow = C + (size_t)m * N + nBase + tx * 8;
        *(float4*)(cRow + 0) = make_float4(o[0], o[1], o[2], o[3]);
        *(float4*)(cRow + 4) = make_float4(o[4], o[5], o[6], o[7]);
    }
}

// ---------------------------------------------------------------------------
// Mirror the computed upper triangle into the lower triangle:
//   sim[i][j] := sim[j][i] for all 128-blocks with colBlock < rowBlock.
// Coalesced 32x32 smem transpose tiles; grid covers 384x384 32-tiles and
// exits early outside the strictly-lower 128-block region.
// ---------------------------------------------------------------------------
__global__ __launch_bounds__(256) void mirror_lower(float* __restrict__ sim)
{
    __shared__ float t[32][33];
    const int tj = blockIdx.x;          // dest 32-tile col index
    const int ti = blockIdx.y;          // dest 32-tile row index
    if ((tj >> 2) >= (ti >> 2)) return; // dest must lie in a strictly-lower 128-block

    const int x = threadIdx.x;          // 0..31
    const int y = threadIdx.y;          // 0..7

    // source tile (upper): rows tj*32.., cols ti*32..
    #pragma unroll
    for (int r = 0; r < 32; r += 8)
        t[y + r][x] = sim[(size_t)(tj * 32 + y + r) * NROWS + ti * 32 + x];
    __syncthreads();
    // dest tile (lower): rows ti*32.., cols tj*32.. ; value = transpose
    #pragma unroll
    for (int r = 0; r < 32; r += 8)
        sim[(size_t)(ti * 32 + y + r) * NROWS + tj * 32 + x] = t[x][y + r];
}

// ---------------------------------------------------------------------------
// Row L2 normalize: e = x / max(||x||, 1e-12). One warp per 256-wide row.
// VERBATIM round-1/9 source — fast-math lowering of this exact expression
// tree is the correlation-critical arithmetic. DO NOT TOUCH.
// ---------------------------------------------------------------------------
__global__ void l2norm_rows(const float* __restrict__ x, float* __restrict__ e)
{
    const int gw   = (blockIdx.x * blockDim.x + threadIdx.x) >> 5;
    const int lane = threadIdx.x & 31;
    if (gw >= NROWS) return;
    const float4* r = (const float4*)(x + (size_t)gw * ODIM);
    float4 v0 = r[lane];
    float4 v1 = r[lane + 32];
    float s = v0.x*v0.x + v0.y*v0.y + v0.z*v0.z + v0.w*v0.w
            + v1.x*v1.x + v1.y*v1.y + v1.z*v1.z + v1.w*v1.w;
    #pragma unroll
    for (int o = 16; o; o >>= 1) s += __shfl_xor_sync(0xFFFFFFFFu, s, o);
    const float scale = 1.0f / fmaxf(sqrtf(s), 1e-12f);
    v0.x *= scale; v0.y *= scale; v0.z *= scale; v0.w *= scale;
    v1.x *= scale; v1.y *= scale; v1.z *= scale; v1.w *= scale;
    float4* w = (float4*)(e + (size_t)gw * ODIM);
    w[lane]      = v0;
    w[lane + 32] = v1;
}

// ---------------------------------------------------------------------------
// Per-row top-31 via exact 4-pass radix select, with lax.top_k-compatible
// tie-breaking: among values bit-equal to the rank-31 threshold, keep only
// the lowest-index occurrences. One CTA per row; row cached in smem.
// ---------------------------------------------------------------------------
#define MAXEQ 64

__global__ __launch_bounds__(256) void topk_rows(const float* __restrict__ sim,
                                                 float* __restrict__ out)
{
    extern __shared__ uint32_t sh[];
    uint32_t* keys = sh;            // NROWS entries (48 KB)
    uint32_t* hist = sh + NROWS;    // 256 entries (1 KB)
    __shared__ uint32_t s_sel, s_rank;
    __shared__ int s_eqIdx[MAXEQ];
    __shared__ int s_eqCnt;
    __shared__ int s_cutoff;

    const int tid  = threadIdx.x;
    const int lane = tid & 31;
    const int row  = blockIdx.x;

    const float4* r4 = (const float4*)(sim + (size_t)row * NROWS);
    for (int i = tid; i < NROWS / 4; i += 256) {
        float4 v = r4[i];
        uint32_t u;
        u = __float_as_uint(v.x); keys[i*4+0] = (u & 0x80000000u) ? ~u : (u | 0x80000000u);
        u = __float_as_uint(v.y); keys[i*4+1] = (u & 0x80000000u) ? ~u : (u | 0x80000000u);
        u = __float_as_uint(v.z); keys[i*4+2] = (u & 0x80000000u) ? ~u : (u | 0x80000000u);
        u = __float_as_uint(v.w); keys[i*4+3] = (u & 0x80000000u) ? ~u : (u | 0x80000000u);
    }
    __syncthreads();

    uint32_t prefix = 0;
    uint32_t rank   = 31;   // KNN_K + 1 entries kept per row

    #pragma unroll
    for (int pass = 0; pass < 4; ++pass) {
        const int      shift = 24 - 8 * pass;
        const uint32_t kmask = (pass == 0) ? 0u : (0xFFFFFFFFu << (shift + 8));

        hist[tid] = 0;
        __syncthreads();

        for (int i = tid; i < NROWS; i += 256) {
            const uint32_t key = keys[i];
            const bool ok = (key & kmask) == prefix;
            const uint32_t d = ok ? ((key >> shift) & 0xFFu) : 0xFFFFFFFFu;
            const unsigned grp = __match_any_sync(0xFFFFFFFFu, d);
            if (ok && lane == (__ffs(grp) - 1))
                atomicAdd(&hist[d], (uint32_t)__popc(grp));
        }
        __syncthreads();

        if (tid == 0) {
            uint32_t c = 0; int d = 255;
            for (; d >= 0; --d) { c += hist[d]; if (c >= rank) break; }
            s_sel  = (uint32_t)d;
            s_rank = rank - (c - hist[d]);
            if (pass == 0) s_eqCnt = 0;
        }
        __syncthreads();
        prefix |= s_sel << shift;
        rank    = s_rank;
    }

    const uint32_t thresh = prefix;   // exact key of 31st-largest value
    const int need = (int)rank;       // # of ==thresh entries that belong in top-31

    // Collect indices of values bit-equal to the threshold (typically 1).
    for (int i = tid; i < NROWS; i += 256) {
        if (keys[i] == thresh) {
            int p = atomicAdd(&s_eqCnt, 1);
            if (p < MAXEQ) s_eqIdx[p] = i;
        }
    }
    __syncthreads();
    if (tid == 0) {
        int cnt = s_eqCnt < MAXEQ ? s_eqCnt : MAXEQ;
        for (int a = 1; a < cnt; a++) {          // tiny ascending insertion sort
            int v = s_eqIdx[a], b = a - 1;
            while (b >= 0 && s_eqIdx[b] > v) { s_eqIdx[b+1] = s_eqIdx[b]; b--; }
            s_eqIdx[b+1] = v;
        }
        int nd = need; if (nd > cnt) nd = cnt; if (nd < 1) nd = 1;
        s_cutoff = s_eqIdx[nd - 1];   // keep ==thresh entries with index <= cutoff
    }
    __syncthreads();
    const int cutoff = s_cutoff;

    float* orow = out + (size_t)row * NROWS;
    for (int i = tid; i < NROWS; i += 256) {
        const uint32_t key = keys[i];
        const bool kept = (key > thresh) | ((key == thresh) & (i <= cutoff));
        float v = 0.0f;
        if (kept && key > 0x80000000u)     // kept AND strictly positive (relu)
            v = __uint_as_float(key ^ 0x80000000u);
        orow[i] = v;
    }
}

// ---------------------------------------------------------------------------
extern "C" void kernel_launch(void* const* d_in, const int* in_sizes, int n_in,
                              void* d_out, int out_size)
{
    const float* features = (const float*)d_in[0];
    const float* W1 = (const float*)d_in[1];
    const float* b1 = (const float*)d_in[2];
    const float* W2 = (const float*)d_in[3];
    const float* b2 = (const float*)d_in[4];
    const float* W3 = (const float*)d_in[5];
    const float* b3 = (const float*)d_in[6];
    float* out = (float*)d_out;

    float *x1, *x2, *e, *sim;
    cudaGetSymbolAddress((void**)&x1,  g_x1);
    cudaGetSymbolAddress((void**)&x2,  g_x2);
    cudaGetSymbolAddress((void**)&e,   g_e);
    cudaGetSymbolAddress((void**)&sim, g_sim);

    cudaFuncSetAttribute(topk_rows, cudaFuncAttributeMaxDynamicSharedMemorySize,
                         (NROWS + 256) * sizeof(uint32_t));

    // MLP (unchanged arithmetic)
    sgemm_abt<1,0><<<dim3(HDIM / 128, NROWS / 128), 256>>>(features, W1, b1, x1, NROWS, HDIM, FDIM);
    sgemm_abt<1,0><<<dim3(HDIM / 128, NROWS / 128), 256>>>(x1,       W2, b2, x2, NROWS, HDIM, HDIM);
    // x3 reuses x1's buffer (x1 is dead after layer 2)
    sgemm_abt<0,0><<<dim3(ODIM / 128, NROWS / 128), 256>>>(x2,       W3, b3, x1, NROWS, ODIM, HDIM);

    // L2 normalize rows -> e (round-1 verbatim)
    l2norm_rows<<<NROWS / 8, 256>>>(x1, e);

    // sim = e @ e^T — upper triangle + diagonal only (bit-identical chain),
    // then mirror the lower triangle (fmaf commutes in its first two args).
    sgemm_abt<0,1><<<dim3(NROWS / 128, NROWS / 128), 256>>>(e, e, nullptr, sim, NROWS, NROWS, ODIM);
    mirror_lower<<<dim3(NROWS / 32, NROWS / 32), dim3(32, 8)>>>(sim);

    // per-row exact top-31 (index tie-break) + masked relu write
    topk_rows<<<NROWS, 256, (NROWS + 256) * sizeof(uint32_t)>>>(sim, out);
}

// round 11
// speedup vs baseline: 1.3645x; 1.0392x over previous
#include <cuda_runtime.h>
#include <cstdint>
#include <cstddef>

#define NROWS 12288
#define FDIM  768
#define HDIM  512
#define ODIM  256

// Scratch (device globals: allocation-free per harness rules)
__device__ float g_x1[(size_t)NROWS * HDIM];          // 24 MB
__device__ float g_x2[(size_t)NROWS * HDIM];          // 24 MB
__device__ float g_e [(size_t)NROWS * ODIM];          // 12 MB
__device__ float g_sim[(size_t)NROWS * NROWS];        // 604 MB

// ---------------------------------------------------------------------------
// SGEMM: C[M,N] = A[M,K] * B[N,K]^T (+bias) (optional relu)
// Per-element arithmetic verbatim from the passing round-9/10 kernel:
// k-ascending single-accumulator fp32 FMA chain, bias added once, relu via
// fmaxf. Double-buffered smem mainloop (ONE __syncthreads per k-tile) — the
// chain order per output element is unchanged, so results are bit-identical.
// SYM=1: tiles with bx<by exit; tiles with bx>by also write their transposed
// image (same o = acc+bj values => bitwise equal, incl. -0+0 => +0).
// Tiles: 128x128x16, 256 threads, 8x8 per-thread microtile.
// ---------------------------------------------------------------------------
template<int RELU, int SYM>
__global__ __launch_bounds__(256) void sgemm_abt(
    const float* __restrict__ A, const float* __restrict__ B,
    const float* __restrict__ bias, float* __restrict__ C,
    int M, int N, int K)
{
    if (SYM && blockIdx.x < blockIdx.y) return;   // lower-triangle tiles mirrored below

    __shared__ __align__(16) float As[2][16][128];
    __shared__ __align__(16) float Bs[2][16][128];

    const int tid = threadIdx.x;
    const int tx  = tid & 15;           // output column group
    const int ty  = tid >> 4;           // output row group
    const int mBase = blockIdx.y * 128;
    const int nBase = blockIdx.x * 128;

    const int r0 = tid >> 2;            // row within tile (0..63)
    const int q0 = (tid & 3) * 4;       // k offset (0,4,8,12)

    const float* aPtr = A + (size_t)(mBase + r0) * K + q0;
    const float* bPtr = B + (size_t)(nBase + r0) * K + q0;

    float acc[8][8];
    #pragma unroll
    for (int i = 0; i < 8; i++)
        #pragma unroll
        for (int j = 0; j < 8; j++) acc[i][j] = 0.0f;

    // Prologue: load k-tile 0 into buffer 0
    {
        float4 a0 = *(const float4*)(aPtr);
        float4 a1 = *(const float4*)(aPtr + (size_t)64 * K);
        float4 b0 = *(const float4*)(bPtr);
        float4 b1 = *(const float4*)(bPtr + (size_t)64 * K);
        As[0][q0+0][r0] = a0.x;  As[0][q0+1][r0] = a0.y;  As[0][q0+2][r0] = a0.z;  As[0][q0+3][r0] = a0.w;
        As[0][q0+0][r0+64] = a1.x; As[0][q0+1][r0+64] = a1.y; As[0][q0+2][r0+64] = a1.z; As[0][q0+3][r0+64] = a1.w;
        Bs[0][q0+0][r0] = b0.x;  Bs[0][q0+1][r0] = b0.y;  Bs[0][q0+2][r0] = b0.z;  Bs[0][q0+3][r0] = b0.w;
        Bs[0][q0+0][r0+64] = b1.x; Bs[0][q0+1][r0+64] = b1.y; Bs[0][q0+2][r0+64] = b1.z; Bs[0][q0+3][r0+64] = b1.w;
    }
    __syncthreads();

    int cur = 0;
    for (int kb = 0; kb < K; kb += 16) {
        const bool hasNext = (kb + 16) < K;
        float4 na0, na1, nb0, nb1;
        if (hasNext) {                    // prefetch next k-tile during compute
            na0 = *(const float4*)(aPtr + kb + 16);
            na1 = *(const float4*)(aPtr + (size_t)64 * K + kb + 16);
            nb0 = *(const float4*)(bPtr + kb + 16);
            nb1 = *(const float4*)(bPtr + (size_t)64 * K + kb + 16);
        }

        #pragma unroll
        for (int k = 0; k < 16; k++) {    // k strictly ascending: chain preserved
            float4 av0 = *(const float4*)&As[cur][k][ty * 8];
            float4 av1 = *(const float4*)&As[cur][k][ty * 8 + 4];
            float4 bv0 = *(const float4*)&Bs[cur][k][tx * 8];
            float4 bv1 = *(const float4*)&Bs[cur][k][tx * 8 + 4];
            float a[8] = {av0.x, av0.y, av0.z, av0.w, av1.x, av1.y, av1.z, av1.w};
            float b[8] = {bv0.x, bv0.y, bv0.z, bv0.w, bv1.x, bv1.y, bv1.z, bv1.w};
            #pragma unroll
            for (int i = 0; i < 8; i++)
                #pragma unroll
                for (int j = 0; j < 8; j++)
                    acc[i][j] = fmaf(a[i], b[j], acc[i][j]);
        }

        if (hasNext) {
            const int nxt = cur ^ 1;      // store prefetch into the idle buffer
            As[nxt][q0+0][r0] = na0.x;  As[nxt][q0+1][r0] = na0.y;  As[nxt][q0+2][r0] = na0.z;  As[nxt][q0+3][r0] = na0.w;
            As[nxt][q0+0][r0+64] = na1.x; As[nxt][q0+1][r0+64] = na1.y; As[nxt][q0+2][r0+64] = na1.z; As[nxt][q0+3][r0+64] = na1.w;
            Bs[nxt][q0+0][r0] = nb0.x;  Bs[nxt][q0+1][r0] = nb0.y;  Bs[nxt][q0+2][r0] = nb0.z;  Bs[nxt][q0+3][r0] = nb0.w;
            Bs[nxt][q0+0][r0+64] = nb1.x; Bs[nxt][q0+1][r0+64] = nb1.y; Bs[nxt][q0+2][r0+64] = nb1.z; Bs[nxt][q0+3][r0+64] = nb1.w;
            __syncthreads();              // single barrier per k-tile
            cur = nxt;
        }
    }

    float bj[8];
    #pragma unroll
    for (int j = 0; j < 8; j++)
        bj[j] = bias ? bias[nBase + tx * 8 + j] : 0.0f;

    #pragma unroll
    for (int i = 0; i < 8; i++) {
        const int m = mBase + ty * 8 + i;
        float o[8];
        #pragma unroll
        for (int j = 0; j < 8; j++) {
            float v = acc[i][j] + bj[j];
            if (RELU) v = fmaxf(v, 0.0f);
            o[j] = v;
        }
        float* cRow = C + (size_t)m * N + nBase + tx * 8;
        *(float4*)(cRow + 0) = make_float4(o[0], o[1], o[2], o[3]);
        *(float4*)(cRow + 4) = make_float4(o[4], o[5], o[6], o[7]);
    }

    // Transposed image for strictly-upper tiles: C[n][m] = acc[i][j] + bj[j]
    // (identical fp ops as the normal store => bitwise equal values).
    if (SYM && blockIdx.x > blockIdx.y) {
        #pragma unroll
        for (int j = 0; j < 8; j++) {
            const int n = nBase + tx * 8 + j;
            float* cRow = C + (size_t)n * N + mBase + ty * 8;
            *(float4*)(cRow + 0) = make_float4(acc[0][j] + bj[j], acc[1][j] + bj[j],
                                               acc[2][j] + bj[j], acc[3][j] + bj[j]);
            *(float4*)(cRow + 4) = make_float4(acc[4][j] + bj[j], acc[5][j] + bj[j],
                                               acc[6][j] + bj[j], acc[7][j] + bj[j]);
        }
    }
}

// ---------------------------------------------------------------------------
// Row L2 normalize: e = x / max(||x||, 1e-12). One warp per 256-wide row.
// VERBATIM round-1/9 source — fast-math lowering of this exact expression
// tree is the correlation-critical arithmetic. DO NOT TOUCH.
// ---------------------------------------------------------------------------
__global__ void l2norm_rows(const float* __restrict__ x, float* __restrict__ e)
{
    const int gw   = (blockIdx.x * blockDim.x + threadIdx.x) >> 5;
    const int lane = threadIdx.x & 31;
    if (gw >= NROWS) return;
    const float4* r = (const float4*)(x + (size_t)gw * ODIM);
    float4 v0 = r[lane];
    float4 v1 = r[lane + 32];
    float s = v0.x*v0.x + v0.y*v0.y + v0.z*v0.z + v0.w*v0.w
            + v1.x*v1.x + v1.y*v1.y + v1.z*v1.z + v1.w*v1.w;
    #pragma unroll
    for (int o = 16; o; o >>= 1) s += __shfl_xor_sync(0xFFFFFFFFu, s, o);
    const float scale = 1.0f / fmaxf(sqrtf(s), 1e-12f);
    v0.x *= scale; v0.y *= scale; v0.z *= scale; v0.w *= scale;
    v1.x *= scale; v1.y *= scale; v1.z *= scale; v1.w *= scale;
    float4* w = (float4*)(e + (size_t)gw * ODIM);
    w[lane]      = v0;
    w[lane + 32] = v1;
}

// ---------------------------------------------------------------------------
// Per-row top-31 via exact 4-pass radix select, with lax.top_k-compatible
// tie-breaking: among values bit-equal to the rank-31 threshold, keep only
// the lowest-index occurrences. One CTA per row; row cached in smem.
// ---------------------------------------------------------------------------
#define MAXEQ 64

__global__ __launch_bounds__(256) void topk_rows(const float* __restrict__ sim,
                                                 float* __restrict__ out)
{
    extern __shared__ uint32_t sh[];
    uint32_t* keys = sh;            // NROWS entries (48 KB)
    uint32_t* hist = sh + NROWS;    // 256 entries (1 KB)
    __shared__ uint32_t s_sel, s_rank;
    __shared__ int s_eqIdx[MAXEQ];
    __shared__ int s_eqCnt;
    __shared__ int s_cutoff;

    const int tid  = threadIdx.x;
    const int lane = tid & 31;
    const int row  = blockIdx.x;

    const float4* r4 = (const float4*)(sim + (size_t)row * NROWS);
    for (int i = tid; i < NROWS / 4; i += 256) {
        float4 v = r4[i];
        uint32_t u;
        u = __float_as_uint(v.x); keys[i*4+0] = (u & 0x80000000u) ? ~u : (u | 0x80000000u);
        u = __float_as_uint(v.y); keys[i*4+1] = (u & 0x80000000u) ? ~u : (u | 0x80000000u);
        u = __float_as_uint(v.z); keys[i*4+2] = (u & 0x80000000u) ? ~u : (u | 0x80000000u);
        u = __float_as_uint(v.w); keys[i*4+3] = (u & 0x80000000u) ? ~u : (u | 0x80000000u);
    }
    __syncthreads();

    uint32_t prefix = 0;
    uint32_t rank   = 31;   // KNN_K + 1 entries kept per row

    #pragma unroll
    for (int pass = 0; pass < 4; ++pass) {
        const int      shift = 24 - 8 * pass;
        const uint32_t kmask = (pass == 0) ? 0u : (0xFFFFFFFFu << (shift + 8));

        hist[tid] = 0;
        __syncthreads();

        for (int i = tid; i < NROWS; i += 256) {
            const uint32_t key = keys[i];
            const bool ok = (key & kmask) == prefix;
            const uint32_t d = ok ? ((key >> shift) & 0xFFu) : 0xFFFFFFFFu;
            const unsigned grp = __match_any_sync(0xFFFFFFFFu, d);
            if (ok && lane == (__ffs(grp) - 1))
                atomicAdd(&hist[d], (uint32_t)__popc(grp));
        }
        __syncthreads();

        if (tid == 0) {
            uint32_t c = 0; int d = 255;
            for (; d >= 0; --d) { c += hist[d]; if (c >= rank) break; }
            s_sel  = (uint32_t)d;
            s_rank = rank - (c - hist[d]);
            if (pass == 0) s_eqCnt = 0;
        }
        __syncthreads();
        prefix |= s_sel << shift;
        rank    = s_rank;
    }

    const uint32_t thresh = prefix;   // exact key of 31st-largest value
    const int need = (int)rank;       // # of ==thresh entries that belong in top-31

    // Collect indices of values bit-equal to the threshold (typically 1).
    for (int i = tid; i < NROWS; i += 256) {
        if (keys[i] == thresh) {
            int p = atomicAdd(&s_eqCnt, 1);
            if (p < MAXEQ) s_eqIdx[p] = i;
        }
    }
    __syncthreads();
    if (tid == 0) {
        int cnt = s_eqCnt < MAXEQ ? s_eqCnt : MAXEQ;
        for (int a = 1; a < cnt; a++) {          // tiny ascending insertion sort
            int v = s_eqIdx[a], b = a - 1;
            while (b >= 0 && s_eqIdx[b] > v) { s_eqIdx[b+1] = s_eqIdx[b]; b--; }
            s_eqIdx[b+1] = v;
        }
        int nd = need; if (nd > cnt) nd = cnt; if (nd < 1) nd = 1;
        s_cutoff = s_eqIdx[nd - 1];   // keep ==thresh entries with index <= cutoff
    }
    __syncthreads();
    const int cutoff = s_cutoff;

    float* orow = out + (size_t)row * NROWS;
    for (int i = tid; i < NROWS; i += 256) {
        const uint32_t key = keys[i];
        const bool kept = (key > thresh) | ((key == thresh) & (i <= cutoff));
        float v = 0.0f;
        if (kept && key > 0x80000000u)     // kept AND strictly positive (relu)
            v = __uint_as_float(key ^ 0x80000000u);
        orow[i] = v;
    }
}

// ---------------------------------------------------------------------------
extern "C" void kernel_launch(void* const* d_in, const int* in_sizes, int n_in,
                              void* d_out, int out_size)
{
    const float* features = (const float*)d_in[0];
    const float* W1 = (const float*)d_in[1];
    const float* b1 = (const float*)d_in[2];
    const float* W2 = (const float*)d_in[3];
    const float* b2 = (const float*)d_in[4];
    const float* W3 = (const float*)d_in[5];
    const float* b3 = (const float*)d_in[6];
    float* out = (float*)d_out;

    float *x1, *x2, *e, *sim;
    cudaGetSymbolAddress((void**)&x1,  g_x1);
    cudaGetSymbolAddress((void**)&x2,  g_x2);
    cudaGetSymbolAddress((void**)&e,   g_e);
    cudaGetSymbolAddress((void**)&sim, g_sim);

    cudaFuncSetAttribute(topk_rows, cudaFuncAttributeMaxDynamicSharedMemorySize,
                         (NROWS + 256) * sizeof(uint32_t));

    // MLP (double-buffered, arithmetic unchanged)
    sgemm_abt<1,0><<<dim3(HDIM / 128, NROWS / 128), 256>>>(features, W1, b1, x1, NROWS, HDIM, FDIM);
    sgemm_abt<1,0><<<dim3(HDIM / 128, NROWS / 128), 256>>>(x1,       W2, b2, x2, NROWS, HDIM, HDIM);
    // x3 reuses x1's buffer (x1 is dead after layer 2)
    sgemm_abt<0,0><<<dim3(ODIM / 128, NROWS / 128), 256>>>(x2,       W3, b3, x1, NROWS, ODIM, HDIM);

    // L2 normalize rows -> e (round-1 verbatim)
    l2norm_rows<<<NROWS / 8, 256>>>(x1, e);

    // sim = e @ e^T — upper triangle + diagonal; off-diagonal tiles write
    // their transposed image directly (bit-identical values, no mirror pass).
    sgemm_abt<0,1><<<dim3(NROWS / 128, NROWS / 128), 256>>>(e, e, nullptr, sim, NROWS, NROWS, ODIM);

    // per-row exact top-31 (index tie-break) + masked relu write
    topk_rows<<<NROWS, 256, (NROWS + 256) * sizeof(uint32_t)>>>(sim, out);
}